// round 15
// baseline (speedup 1.0000x reference)
#include <cuda_runtime.h>
#include <cuda_bf16.h>
#include <cuda_fp16.h>
#include <stdint.h>
#include <math.h>

#define N_NODES 100000
#define N_EDGES 1600000
#define F_IN 128
#define D_OUT 64
#define PADK 136   // bf16 elems per smem row (272B stride)
#define CAP 64     // fixed per-node edge capacity (Poisson(16): P(deg>=64) ~ 1e-24)

static __device__ __constant__ float c_eps = 1e-3f;

// ---------------- scratch ------------------------------------------------------
__device__ float g_colsum[F_IN];    // self-zeroed by finalize for replay
__device__ float g_colsq[F_IN];
__device__ float g_mean[F_IN];
__device__ float g_rstd[F_IN];
__device__ float g_a1[N_NODES];
__device__ float g_a2[N_NODES];
__device__ __half2 g_mapped16[(size_t)N_NODES * 32];
__device__ int   g_cur[N_NODES];               // self-zeroed by spmm for replay
__device__ int2  g_cedge[(size_t)N_NODES * CAP];

// ---------------- colstats (measured 17.9us) -------------------------------------
__global__ void k_colstats(const float* __restrict__ x) {
    __shared__ float ssum[8][128];
    __shared__ float ssq[8][128];
    int w = threadIdx.x >> 5, lane = threadIdx.x & 31;
    float4 s = make_float4(0.f, 0.f, 0.f, 0.f);
    float4 q = make_float4(0.f, 0.f, 0.f, 0.f);
    #pragma unroll 4
    for (int row = blockIdx.x * 8 + w; row < N_NODES; row += gridDim.x * 8) {
        float4 v = ((const float4*)x)[(size_t)row * 32 + lane];
        s.x += v.x; s.y += v.y; s.z += v.z; s.w += v.w;
        q.x += v.x * v.x; q.y += v.y * v.y; q.z += v.z * v.z; q.w += v.w * v.w;
    }
    *(float4*)&ssum[w][lane * 4] = s;
    *(float4*)&ssq[w][lane * 4] = q;
    __syncthreads();
    if (threadIdx.x < 128) {
        float ts = 0.f, tq = 0.f;
        #pragma unroll
        for (int ww = 0; ww < 8; ++ww) { ts += ssum[ww][threadIdx.x]; tq += ssq[ww][threadIdx.x]; }
        atomicAdd(&g_colsum[threadIdx.x], ts);
        atomicAdd(&g_colsq[threadIdx.x], tq);
    }
}

__global__ void k_finalize_stats() {
    int f = threadIdx.x;
    float mean = g_colsum[f] / (float)N_NODES;
    float var  = g_colsq[f] / (float)N_NODES - mean * mean;
    g_mean[f] = mean;
    g_rstd[f] = rsqrtf(var + c_eps);
    g_colsum[f] = 0.f;
    g_colsq[f] = 0.f;
}

// ---------------- scatter into fixed-capacity CSR (no hist/scan needed) ---------
__global__ void k_scatter(const int* __restrict__ src, const int* __restrict__ dst,
                          const float* __restrict__ vals) {
    int i = blockIdx.x * blockDim.x + threadIdx.x;
    if (i < N_EDGES) {
        int s = src[i];
        int p = atomicAdd(&g_cur[s], 1);
        if (p < CAP)
            g_cedge[(size_t)s * CAP + p] = make_int2(dst[i], __float_as_int(vals[i]));
    }
}

// ---------------- tensor-core GEMM (exact R10 math: bf16 3-term, fp16 mapped) ---
__device__ __forceinline__ void bsplit(float v, __nv_bfloat16& h, __nv_bfloat16& l) {
    h = __float2bfloat16(v);
    l = __float2bfloat16(v - __bfloat162float(h));
}

#define MMA16816(D, A, B0, B1)                                               \
    asm volatile(                                                            \
        "mma.sync.aligned.m16n8k16.row.col.f32.bf16.bf16.f32 "              \
        "{%0,%1,%2,%3}, {%4,%5,%6,%7}, {%8,%9}, {%0,%1,%2,%3};"             \
        : "+f"(D[0]), "+f"(D[1]), "+f"(D[2]), "+f"(D[3])                     \
        : "r"(A[0]), "r"(A[1]), "r"(A[2]), "r"(A[3]), "r"(B0), "r"(B1))

#define LDSM4(R0, R1, R2, R3, ADDR)                                          \
    asm volatile("ldmatrix.sync.aligned.m8n8.x4.shared.b16 {%0,%1,%2,%3}, [%4];" \
        : "=r"(R0), "=r"(R1), "=r"(R2), "=r"(R3) : "r"(ADDR))

__global__ void __launch_bounds__(256, 1) k_gemm(
    const float* __restrict__ x, const float* __restrict__ K1,
    const float* __restrict__ K2, const float* __restrict__ W)
{
    extern __shared__ __nv_bfloat16 smem[];
    __nv_bfloat16* sK1h = smem;                    // [128][PADK]
    __nv_bfloat16* sK1l = sK1h + F_IN * PADK;
    __nv_bfloat16* sK2h = sK1l + F_IN * PADK;
    __nv_bfloat16* sK2l = sK2h + F_IN * PADK;
    __nv_bfloat16* sWh  = sK2l + F_IN * PADK;      // [64][PADK]
    __nv_bfloat16* sWl  = sWh + D_OUT * PADK;
    __nv_bfloat16* sXh  = sWl + D_OUT * PADK;      // [64][PADK]
    __nv_bfloat16* sXl  = sXh + 64 * PADK;
    float* sD1 = (float*)(sXl + 64 * PADK);        // [64][2]
    float* sD2 = sD1 + 128;

    int tid = threadIdx.x;

    for (int i = tid; i < F_IN * F_IN; i += 256) {
        int k = i >> 7, n = i & 127;
        __nv_bfloat16 h, l;
        bsplit(K1[i], h, l); sK1h[n * PADK + k] = h; sK1l[n * PADK + k] = l;
        bsplit(K2[i], h, l); sK2h[n * PADK + k] = h; sK2l[n * PADK + k] = l;
    }
    for (int i = tid; i < F_IN * D_OUT; i += 256) {
        int k = i >> 6, n = i & 63;
        __nv_bfloat16 h, l;
        bsplit(W[i], h, l); sWh[n * PADK + k] = h; sWl[n * PADK + k] = l;
    }

    int w = tid >> 5, lane = tid & 31;
    int g = lane >> 2, tig = lane & 3;
    int wr = w >> 1, wc = w & 1;
    int r0 = wr * 16;

    uint32_t sXh_s = (uint32_t)__cvta_generic_to_shared(sXh);
    uint32_t sXl_s = (uint32_t)__cvta_generic_to_shared(sXl);
    uint32_t sK1h_s = (uint32_t)__cvta_generic_to_shared(sK1h);
    uint32_t sK1l_s = (uint32_t)__cvta_generic_to_shared(sK1l);
    uint32_t sK2h_s = (uint32_t)__cvta_generic_to_shared(sK2h);
    uint32_t sK2l_s = (uint32_t)__cvta_generic_to_shared(sK2l);
    uint32_t sWh_s  = (uint32_t)__cvta_generic_to_shared(sWh);
    uint32_t sWl_s  = (uint32_t)__cvta_generic_to_shared(sWl);

    int aRow = r0 + (lane & 7) + ((lane >> 3) & 1) * 8;
    int aKof = (lane >> 4) * 8;
    uint32_t aByte = (uint32_t)(aRow * PADK + aKof) * 2;
    int bRow = lane & 7;
    int bKof = ((lane >> 3) & 1) * 8;
    int bLo  = (lane >> 4) & 1;
    uint32_t bByte = (uint32_t)(bRow * PADK + bKof) * 2;

    float4 mn = ((const float4*)g_mean)[lane];
    float4 rs = ((const float4*)g_rstd)[lane];

    const int ntiles = (N_NODES + 63) / 64;
    for (int tile = blockIdx.x; tile < ntiles; tile += gridDim.x) {
        int node0 = tile * 64;
        __syncthreads();

        #pragma unroll
        for (int rr = 0; rr < 8; ++rr) {
            int r = w * 8 + rr;
            int gn = node0 + r;
            float4 xv = make_float4(0.f, 0.f, 0.f, 0.f);
            if (gn < N_NODES) xv = ((const float4*)x)[(size_t)gn * (F_IN / 4) + lane];
            float xn[4];
            xn[0] = (xv.x - mn.x) * rs.x;
            xn[1] = (xv.y - mn.y) * rs.y;
            xn[2] = (xv.z - mn.z) * rs.z;
            xn[3] = (xv.w - mn.w) * rs.w;
            __nv_bfloat16 h[4], l[4];
            #pragma unroll
            for (int c = 0; c < 4; ++c) bsplit(xn[c], h[c], l[c]);
            int base = r * PADK + 4 * lane;
            *(__nv_bfloat162*)&sXh[base]     = __nv_bfloat162(h[0], h[1]);
            *(__nv_bfloat162*)&sXh[base + 2] = __nv_bfloat162(h[2], h[3]);
            *(__nv_bfloat162*)&sXl[base]     = __nv_bfloat162(l[0], l[1]);
            *(__nv_bfloat162*)&sXl[base + 2] = __nv_bfloat162(l[2], l[3]);
        }
        __syncthreads();

        float aK1[8][4], aK2[8][4], aW[4][4];
        #pragma unroll
        for (int t = 0; t < 8; ++t)
            #pragma unroll
            for (int i = 0; i < 4; ++i) { aK1[t][i] = 0.f; aK2[t][i] = 0.f; }
        #pragma unroll
        for (int t = 0; t < 4; ++t)
            #pragma unroll
            for (int i = 0; i < 4; ++i) aW[t][i] = 0.f;

        #pragma unroll
        for (int ks = 0; ks < 8; ++ks) {
            uint32_t k0b = (uint32_t)(ks * 16) * 2;
            uint32_t ah[4], al[4];
            LDSM4(ah[0], ah[1], ah[2], ah[3], sXh_s + aByte + k0b);
            LDSM4(al[0], al[1], al[2], al[3], sXl_s + aByte + k0b);

            #pragma unroll
            for (int t = 0; t < 8; ++t) {
                int n0 = wc * 64 + t * 8;
                uint32_t addr = (bLo ? sK1l_s : sK1h_s) + bByte + (uint32_t)(n0 * PADK) * 2 + k0b;
                uint32_t bh0, bh1, bl0, bl1;
                LDSM4(bh0, bh1, bl0, bl1, addr);
                MMA16816(aK1[t], ah, bh0, bh1);
                MMA16816(aK1[t], ah, bl0, bl1);
                MMA16816(aK1[t], al, bh0, bh1);
            }
            #pragma unroll
            for (int t = 0; t < 8; ++t) {
                int n0 = wc * 64 + t * 8;
                uint32_t addr = (bLo ? sK2l_s : sK2h_s) + bByte + (uint32_t)(n0 * PADK) * 2 + k0b;
                uint32_t bh0, bh1, bl0, bl1;
                LDSM4(bh0, bh1, bl0, bl1, addr);
                MMA16816(aK2[t], ah, bh0, bh1);
                MMA16816(aK2[t], ah, bl0, bl1);
                MMA16816(aK2[t], al, bh0, bh1);
            }
            #pragma unroll
            for (int t = 0; t < 4; ++t) {
                int n0 = wc * 32 + t * 8;
                uint32_t addr = (bLo ? sWl_s : sWh_s) + bByte + (uint32_t)(n0 * PADK) * 2 + k0b;
                uint32_t bh0, bh1, bl0, bl1;
                LDSM4(bh0, bh1, bl0, bl1, addr);
                MMA16816(aW[t], ah, bh0, bh1);
                MMA16816(aW[t], ah, bl0, bl1);
                MMA16816(aW[t], al, bh0, bh1);
            }
        }

        {
            int rA = r0 + g, rB = r0 + g + 8;
            float p0 = 0.f, p1 = 0.f, q0 = 0.f, q1 = 0.f;
            #pragma unroll
            for (int t = 0; t < 8; ++t) {
                int c0 = wc * 64 + t * 8 + 2 * tig;
                float2 hA = __bfloat1622float2(*(const __nv_bfloat162*)&sXh[rA * PADK + c0]);
                float2 lA = __bfloat1622float2(*(const __nv_bfloat162*)&sXl[rA * PADK + c0]);
                float2 hB = __bfloat1622float2(*(const __nv_bfloat162*)&sXh[rB * PADK + c0]);
                float2 lB = __bfloat1622float2(*(const __nv_bfloat162*)&sXl[rB * PADK + c0]);
                float xA0 = hA.x + lA.x, xA1 = hA.y + lA.y;
                float xB0 = hB.x + lB.x, xB1 = hB.y + lB.y;
                p0 += aK1[t][0] * xA0 + aK1[t][1] * xA1;
                p1 += aK1[t][2] * xB0 + aK1[t][3] * xB1;
                q0 += aK2[t][0] * xA0 + aK2[t][1] * xA1;
                q1 += aK2[t][2] * xB0 + aK2[t][3] * xB1;
            }
            p0 += __shfl_xor_sync(0xffffffffu, p0, 1); p0 += __shfl_xor_sync(0xffffffffu, p0, 2);
            p1 += __shfl_xor_sync(0xffffffffu, p1, 1); p1 += __shfl_xor_sync(0xffffffffu, p1, 2);
            q0 += __shfl_xor_sync(0xffffffffu, q0, 1); q0 += __shfl_xor_sync(0xffffffffu, q0, 2);
            q1 += __shfl_xor_sync(0xffffffffu, q1, 1); q1 += __shfl_xor_sync(0xffffffffu, q1, 2);
            if (tig == 0) {
                sD1[rA * 2 + wc] = p0; sD1[rB * 2 + wc] = p1;
                sD2[rA * 2 + wc] = q0; sD2[rB * 2 + wc] = q1;
            }
        }

        #pragma unroll
        for (int t = 0; t < 4; ++t) {
            int c0 = wc * 32 + t * 8 + 2 * tig;
            int gA = node0 + r0 + g, gB = gA + 8;
            if (gA < N_NODES)
                g_mapped16[(size_t)gA * 32 + (c0 >> 1)] = __floats2half2_rn(aW[t][0], aW[t][1]);
            if (gB < N_NODES)
                g_mapped16[(size_t)gB * 32 + (c0 >> 1)] = __floats2half2_rn(aW[t][2], aW[t][3]);
        }

        __syncthreads();
        if (tid < 64) {
            int gn = node0 + tid;
            if (gn < N_NODES) {
                g_a1[gn] = tanhf(sD1[tid * 2] + sD1[tid * 2 + 1]);
                g_a2[gn] = tanhf(sD2[tid * 2] + sD2[tid * 2 + 1]);
            }
        }
    }
}

// ---------------- fused softmax + SpMM + tanh (R10 inner loop; fixed CSR) -------
__global__ void k_spmm(float* __restrict__ out) {
    __shared__ int2 sed[8][32];
    int w = threadIdx.x >> 5;
    int node = blockIdx.x * 8 + w;
    if (node >= N_NODES) return;
    int lane = threadIdx.x & 31;

    // read per-node count; lane 0 re-zeroes it for the next graph replay
    int deg = 0;
    if (lane == 0) {
        deg = g_cur[node];
        g_cur[node] = 0;
    }
    deg = __shfl_sync(0xffffffffu, deg, 0);
    deg = min(deg, CAP);
    int s = node * CAP;
    int e = s + deg;
    float a1i = g_a1[node];

    float2 acc = make_float2(0.f, 0.f);
    float den = 0.f;

    for (int base = s; base < e; base += 32) {
        int j = base + lane;
        int d = 0; float wgt = 0.f;
        if (j < e) {
            int2 ed = g_cedge[j];
            d = ed.x;
            float v = __int_as_float(ed.y);
            float t = v * (a1i + g_a2[d]);
            t = t > 0.f ? t : 0.2f * t;
            wgt = __expf(t);
        }
        sed[w][lane] = make_int2(d, __float_as_int(wgt));
        __syncwarp();
        int m = min(32, e - base);
        #pragma unroll 4
        for (int jj = 0; jj < m; ++jj) {
            int2 ed = sed[w][jj];
            float wj = __int_as_float(ed.y);
            float2 md = __half22float2(g_mapped16[(size_t)ed.x * 32 + lane]);
            den += wj;
            acc.x += wj * md.x;
            acc.y += wj * md.y;
        }
        __syncwarp();
    }
    float2 o;
    if (deg > 0) {
        float inv = 1.f / den;
        o.x = tanhf(acc.x * inv);
        o.y = tanhf(acc.y * inv);
    } else {
        o = make_float2(0.f, 0.f);
    }
    ((float2*)out)[(size_t)node * 32 + lane] = o;
}

// ---------------- launch: 5 kernels ----------------------------------------------
// scatter(s2) || colstats -> finalize -> gemm(main, slot 4 = profiled); spmm joins.
extern "C" void kernel_launch(void* const* d_in, const int* in_sizes, int n_in,
                              void* d_out, int out_size) {
    const float* x    = (const float*)d_in[0];
    const int*   src  = (const int*)d_in[1];
    const int*   dst  = (const int*)d_in[2];
    const float* vals = (const float*)d_in[3];
    const float* W    = (const float*)d_in[4];
    const float* K1   = (const float*)d_in[5];
    const float* K2   = (const float*)d_in[6];
    float* out = (float*)d_out;

    static cudaStream_t s2 = nullptr;
    static cudaEvent_t evA = nullptr, evB = nullptr;
    if (!s2) {
        cudaStreamCreateWithFlags(&s2, cudaStreamNonBlocking);
        cudaEventCreateWithFlags(&evA, cudaEventDisableTiming);
        cudaEventCreateWithFlags(&evB, cudaEventDisableTiming);
    }

    const int EB = (N_EDGES + 255) / 256;

    cudaEventRecord(evA, 0);
    cudaStreamWaitEvent(s2, evA, 0);

    k_scatter<<<EB, 256, 0, s2>>>(src, dst, vals);   // 1 (s2)
    cudaEventRecord(evB, s2);

    k_colstats<<<592, 256>>>(x);                     // 2 (main)
    k_finalize_stats<<<1, 128>>>();                  // 3 (main)
    size_t smem = (size_t)(4 * F_IN * PADK + 2 * D_OUT * PADK + 2 * 64 * PADK) * sizeof(__nv_bfloat16)
                + 256 * sizeof(float);
    cudaFuncSetAttribute(k_gemm, cudaFuncAttributeMaxDynamicSharedMemorySize, (int)smem);
    k_gemm<<<148, 256, smem>>>(x, K1, K2, W);        // 4 (main) <-- profiled

    cudaStreamWaitEvent(0, evB, 0);
    k_spmm<<<(N_NODES + 7) / 8, 256>>>(out);         // 5 (main)
}

// round 16
// speedup vs baseline: 2.2422x; 2.2422x over previous
#include <cuda_runtime.h>
#include <cuda_bf16.h>
#include <cuda_fp16.h>
#include <stdint.h>
#include <math.h>

#define N_NODES 100000
#define N_EDGES 1600000
#define F_IN 128
#define D_OUT 64
#define PADK 136   // bf16 elems per smem row (272B stride)

static __device__ __constant__ float c_eps = 1e-3f;

// ---------------- scratch ------------------------------------------------------
__device__ float g_colsum[F_IN];    // self-zeroed by finalize for replay
__device__ float g_colsq[F_IN];
__device__ float g_mean[F_IN];
__device__ float g_rstd[F_IN];
__device__ float g_a1[N_NODES];
__device__ float g_a2[N_NODES];
__device__ __half2 g_mapped16[(size_t)N_NODES * 32];
__device__ int   g_deg[N_NODES];
__device__ int   g_cur[N_NODES];
__device__ int   g_rowptr[N_NODES + 1];
__device__ int   g_bsum[128];
__device__ int   g_bscan[128];
__device__ int2  g_cedge[N_EDGES];   // packed CSR (validated layout)

// ---------------- colstats (measured 17.9us) -------------------------------------
__global__ void k_colstats(const float* __restrict__ x) {
    __shared__ float ssum[8][128];
    __shared__ float ssq[8][128];
    int w = threadIdx.x >> 5, lane = threadIdx.x & 31;
    float4 s = make_float4(0.f, 0.f, 0.f, 0.f);
    float4 q = make_float4(0.f, 0.f, 0.f, 0.f);
    #pragma unroll 4
    for (int row = blockIdx.x * 8 + w; row < N_NODES; row += gridDim.x * 8) {
        float4 v = ((const float4*)x)[(size_t)row * 32 + lane];
        s.x += v.x; s.y += v.y; s.z += v.z; s.w += v.w;
        q.x += v.x * v.x; q.y += v.y * v.y; q.z += v.z * v.z; q.w += v.w * v.w;
    }
    *(float4*)&ssum[w][lane * 4] = s;
    *(float4*)&ssq[w][lane * 4] = q;
    __syncthreads();
    if (threadIdx.x < 128) {
        float ts = 0.f, tq = 0.f;
        #pragma unroll
        for (int ww = 0; ww < 8; ++ww) { ts += ssum[ww][threadIdx.x]; tq += ssq[ww][threadIdx.x]; }
        atomicAdd(&g_colsum[threadIdx.x], ts);
        atomicAdd(&g_colsq[threadIdx.x], tq);
    }
}

__global__ void k_finalize_stats() {
    int f = threadIdx.x;
    float mean = g_colsum[f] / (float)N_NODES;
    float var  = g_colsq[f] / (float)N_NODES - mean * mean;
    g_mean[f] = mean;
    g_rstd[f] = rsqrtf(var + c_eps);
    g_colsum[f] = 0.f;
    g_colsq[f] = 0.f;
}

__global__ void k_zero_deg() {
    int i = blockIdx.x * blockDim.x + threadIdx.x;
    int stride = gridDim.x * blockDim.x;
    for (; i < N_NODES; i += stride) g_deg[i] = 0;
}

__global__ void k_hist(const int* __restrict__ src) {
    int i = blockIdx.x * blockDim.x + threadIdx.x;
    if (i < N_EDGES) atomicAdd(&g_deg[src[i]], 1);
}

__global__ void k_scan1() {
    __shared__ int sh[1024];
    int tid = threadIdx.x;
    int i = blockIdx.x * 1024 + tid;
    int v = (i < N_NODES) ? g_deg[i] : 0;
    sh[tid] = v;
    __syncthreads();
    for (int off = 1; off < 1024; off <<= 1) {
        int t = (tid >= off) ? sh[tid - off] : 0;
        __syncthreads();
        sh[tid] += t;
        __syncthreads();
    }
    if (i < N_NODES) g_rowptr[i + 1] = sh[tid];
    if (tid == 1023) g_bsum[blockIdx.x] = sh[1023];
}

__global__ void k_scan2(int nb) {
    __shared__ int sh[128];
    int t = threadIdx.x;
    int v = (t < nb) ? g_bsum[t] : 0;
    sh[t] = v;
    __syncthreads();
    for (int off = 1; off < 128; off <<= 1) {
        int u = (t >= off) ? sh[t - off] : 0;
        __syncthreads();
        sh[t] += u;
        __syncthreads();
    }
    if (t < nb) g_bscan[t] = sh[t];
}

__global__ void k_scan3() {
    int tid = threadIdx.x;
    int i = blockIdx.x * 1024 + tid;
    int add = (blockIdx.x > 0) ? g_bscan[blockIdx.x - 1] : 0;
    if (i < N_NODES) {
        g_rowptr[i + 1] += add;
        g_cur[i] = 0;
    }
    if (i == 0) g_rowptr[0] = 0;
}

__global__ void k_scatter(const int* __restrict__ src, const int* __restrict__ dst,
                          const float* __restrict__ vals) {
    int i = blockIdx.x * blockDim.x + threadIdx.x;
    if (i < N_EDGES) {
        int s = src[i];
        int p = g_rowptr[s] + atomicAdd(&g_cur[s], 1);
        g_cedge[p] = make_int2(dst[i], __float_as_int(vals[i]));
    }
}

// ---------------- tensor-core GEMM: bf16 3-term; warp = 32 rows x 32 cols -------
// B fragments now serve 2 row-groups each: LDSM per k-step per warp 22 -> 14.
__device__ __forceinline__ void bsplit(float v, __nv_bfloat16& h, __nv_bfloat16& l) {
    h = __float2bfloat16(v);
    l = __float2bfloat16(v - __bfloat162float(h));
}

#define MMA16816(D, A, B0, B1)                                               \
    asm volatile(                                                            \
        "mma.sync.aligned.m16n8k16.row.col.f32.bf16.bf16.f32 "              \
        "{%0,%1,%2,%3}, {%4,%5,%6,%7}, {%8,%9}, {%0,%1,%2,%3};"             \
        : "+f"(D[0]), "+f"(D[1]), "+f"(D[2]), "+f"(D[3])                     \
        : "r"(A[0]), "r"(A[1]), "r"(A[2]), "r"(A[3]), "r"(B0), "r"(B1))

#define LDSM4(R0, R1, R2, R3, ADDR)                                          \
    asm volatile("ldmatrix.sync.aligned.m8n8.x4.shared.b16 {%0,%1,%2,%3}, [%4];" \
        : "=r"(R0), "=r"(R1), "=r"(R2), "=r"(R3) : "r"(ADDR))

__global__ void __launch_bounds__(256, 1) k_gemm(
    const float* __restrict__ x, const float* __restrict__ K1,
    const float* __restrict__ K2, const float* __restrict__ W)
{
    extern __shared__ __nv_bfloat16 smem[];
    __nv_bfloat16* sK1h = smem;                    // [128][PADK]
    __nv_bfloat16* sK1l = sK1h + F_IN * PADK;
    __nv_bfloat16* sK2h = sK1l + F_IN * PADK;
    __nv_bfloat16* sK2l = sK2h + F_IN * PADK;
    __nv_bfloat16* sWh  = sK2l + F_IN * PADK;      // [64][PADK]
    __nv_bfloat16* sWl  = sWh + D_OUT * PADK;
    __nv_bfloat16* sXh  = sWl + D_OUT * PADK;      // [64][PADK]
    __nv_bfloat16* sXl  = sXh + 64 * PADK;
    float* sD1 = (float*)(sXl + 64 * PADK);        // [64][4]
    float* sD2 = sD1 + 256;                        // [64][4]

    int tid = threadIdx.x;

    for (int i = tid; i < F_IN * F_IN; i += 256) {
        int k = i >> 7, n = i & 127;
        __nv_bfloat16 h, l;
        bsplit(K1[i], h, l); sK1h[n * PADK + k] = h; sK1l[n * PADK + k] = l;
        bsplit(K2[i], h, l); sK2h[n * PADK + k] = h; sK2l[n * PADK + k] = l;
    }
    for (int i = tid; i < F_IN * D_OUT; i += 256) {
        int k = i >> 6, n = i & 63;
        __nv_bfloat16 h, l;
        bsplit(W[i], h, l); sWh[n * PADK + k] = h; sWl[n * PADK + k] = l;
    }

    int w = tid >> 5, lane = tid & 31;
    int g = lane >> 2, tig = lane & 3;
    int wr = w >> 2, wc = w & 3;          // 2 row-blocks x 4 col-slices
    int r0 = wr * 32;                     // warp covers rows r0..r0+31

    uint32_t sXh_s = (uint32_t)__cvta_generic_to_shared(sXh);
    uint32_t sXl_s = (uint32_t)__cvta_generic_to_shared(sXl);
    uint32_t sK1h_s = (uint32_t)__cvta_generic_to_shared(sK1h);
    uint32_t sK1l_s = (uint32_t)__cvta_generic_to_shared(sK1l);
    uint32_t sK2h_s = (uint32_t)__cvta_generic_to_shared(sK2h);
    uint32_t sK2l_s = (uint32_t)__cvta_generic_to_shared(sK2l);
    uint32_t sWh_s  = (uint32_t)__cvta_generic_to_shared(sWh);
    uint32_t sWl_s  = (uint32_t)__cvta_generic_to_shared(sWl);

    int aRow = r0 + (lane & 7) + ((lane >> 3) & 1) * 8;
    int aKof = (lane >> 4) * 8;
    uint32_t aByte = (uint32_t)(aRow * PADK + aKof) * 2;
    const uint32_t RG = (uint32_t)(16 * PADK) * 2;       // row-group byte stride
    int bRow = lane & 7;
    int bKof = ((lane >> 3) & 1) * 8;
    int bLo  = (lane >> 4) & 1;
    uint32_t bByte = (uint32_t)(bRow * PADK + bKof) * 2;

    float4 mn = ((const float4*)g_mean)[lane];
    float4 rs = ((const float4*)g_rstd)[lane];

    const int ntiles = (N_NODES + 63) / 64;
    for (int tile = blockIdx.x; tile < ntiles; tile += gridDim.x) {
        int node0 = tile * 64;
        __syncthreads();

        #pragma unroll
        for (int rr = 0; rr < 8; ++rr) {
            int r = w * 8 + rr;
            int gn = node0 + r;
            float4 xv = make_float4(0.f, 0.f, 0.f, 0.f);
            if (gn < N_NODES) xv = ((const float4*)x)[(size_t)gn * (F_IN / 4) + lane];
            float xn[4];
            xn[0] = (xv.x - mn.x) * rs.x;
            xn[1] = (xv.y - mn.y) * rs.y;
            xn[2] = (xv.z - mn.z) * rs.z;
            xn[3] = (xv.w - mn.w) * rs.w;
            __nv_bfloat16 h[4], l[4];
            #pragma unroll
            for (int c = 0; c < 4; ++c) bsplit(xn[c], h[c], l[c]);
            int base = r * PADK + 4 * lane;
            *(__nv_bfloat162*)&sXh[base]     = __nv_bfloat162(h[0], h[1]);
            *(__nv_bfloat162*)&sXh[base + 2] = __nv_bfloat162(h[2], h[3]);
            *(__nv_bfloat162*)&sXl[base]     = __nv_bfloat162(l[0], l[1]);
            *(__nv_bfloat162*)&sXl[base + 2] = __nv_bfloat162(l[2], l[3]);
        }
        __syncthreads();

        // accumulators: [t-group*2 + rowgroup][4]
        float aK1[8][4], aK2[8][4], aW[4][4];
        #pragma unroll
        for (int t = 0; t < 8; ++t)
            #pragma unroll
            for (int i = 0; i < 4; ++i) { aK1[t][i] = 0.f; aK2[t][i] = 0.f; }
        #pragma unroll
        for (int t = 0; t < 4; ++t)
            #pragma unroll
            for (int i = 0; i < 4; ++i) aW[t][i] = 0.f;

        #pragma unroll
        for (int ks = 0; ks < 8; ++ks) {
            uint32_t k0b = (uint32_t)(ks * 16) * 2;
            uint32_t ah0[4], al0[4], ah1[4], al1[4];
            LDSM4(ah0[0], ah0[1], ah0[2], ah0[3], sXh_s + aByte + k0b);
            LDSM4(al0[0], al0[1], al0[2], al0[3], sXl_s + aByte + k0b);
            LDSM4(ah1[0], ah1[1], ah1[2], ah1[3], sXh_s + aByte + RG + k0b);
            LDSM4(al1[0], al1[1], al1[2], al1[3], sXl_s + aByte + RG + k0b);

            #pragma unroll
            for (int t = 0; t < 4; ++t) {      // K1: cols wc*32 + t*8
                uint32_t addr = (bLo ? sK1l_s : sK1h_s) + bByte
                              + (uint32_t)((wc * 32 + t * 8) * PADK) * 2 + k0b;
                uint32_t bh0, bh1, bl0, bl1;
                LDSM4(bh0, bh1, bl0, bl1, addr);
                MMA16816(aK1[t * 2],     ah0, bh0, bh1);
                MMA16816(aK1[t * 2],     ah0, bl0, bl1);
                MMA16816(aK1[t * 2],     al0, bh0, bh1);
                MMA16816(aK1[t * 2 + 1], ah1, bh0, bh1);
                MMA16816(aK1[t * 2 + 1], ah1, bl0, bl1);
                MMA16816(aK1[t * 2 + 1], al1, bh0, bh1);
            }
            #pragma unroll
            for (int t = 0; t < 4; ++t) {      // K2
                uint32_t addr = (bLo ? sK2l_s : sK2h_s) + bByte
                              + (uint32_t)((wc * 32 + t * 8) * PADK) * 2 + k0b;
                uint32_t bh0, bh1, bl0, bl1;
                LDSM4(bh0, bh1, bl0, bl1, addr);
                MMA16816(aK2[t * 2],     ah0, bh0, bh1);
                MMA16816(aK2[t * 2],     ah0, bl0, bl1);
                MMA16816(aK2[t * 2],     al0, bh0, bh1);
                MMA16816(aK2[t * 2 + 1], ah1, bh0, bh1);
                MMA16816(aK2[t * 2 + 1], ah1, bl0, bl1);
                MMA16816(aK2[t * 2 + 1], al1, bh0, bh1);
            }
            #pragma unroll
            for (int t = 0; t < 2; ++t) {      // W: cols wc*16 + t*8
                uint32_t addr = (bLo ? sWl_s : sWh_s) + bByte
                              + (uint32_t)((wc * 16 + t * 8) * PADK) * 2 + k0b;
                uint32_t bh0, bh1, bl0, bl1;
                LDSM4(bh0, bh1, bl0, bl1, addr);
                MMA16816(aW[t * 2],     ah0, bh0, bh1);
                MMA16816(aW[t * 2],     ah0, bl0, bl1);
                MMA16816(aW[t * 2],     al0, bh0, bh1);
                MMA16816(aW[t * 2 + 1], ah1, bh0, bh1);
                MMA16816(aW[t * 2 + 1], ah1, bl0, bl1);
                MMA16816(aW[t * 2 + 1], al1, bh0, bh1);
            }
        }

        // ---- quadratic-form rowdots (4 row positions per warp) ----
        {
            float p[4] = {0.f, 0.f, 0.f, 0.f};
            float q[4] = {0.f, 0.f, 0.f, 0.f};
            #pragma unroll
            for (int t = 0; t < 4; ++t) {
                int c0 = wc * 32 + t * 8 + 2 * tig;
                #pragma unroll
                for (int rg = 0; rg < 2; ++rg) {
                    int rA = r0 + rg * 16 + g, rB = rA + 8;
                    float2 hA = __bfloat1622float2(*(const __nv_bfloat162*)&sXh[rA * PADK + c0]);
                    float2 lA = __bfloat1622float2(*(const __nv_bfloat162*)&sXl[rA * PADK + c0]);
                    float2 hB = __bfloat1622float2(*(const __nv_bfloat162*)&sXh[rB * PADK + c0]);
                    float2 lB = __bfloat1622float2(*(const __nv_bfloat162*)&sXl[rB * PADK + c0]);
                    float xA0 = hA.x + lA.x, xA1 = hA.y + lA.y;
                    float xB0 = hB.x + lB.x, xB1 = hB.y + lB.y;
                    p[rg * 2 + 0] += aK1[t * 2 + rg][0] * xA0 + aK1[t * 2 + rg][1] * xA1;
                    p[rg * 2 + 1] += aK1[t * 2 + rg][2] * xB0 + aK1[t * 2 + rg][3] * xB1;
                    q[rg * 2 + 0] += aK2[t * 2 + rg][0] * xA0 + aK2[t * 2 + rg][1] * xA1;
                    q[rg * 2 + 1] += aK2[t * 2 + rg][2] * xB0 + aK2[t * 2 + rg][3] * xB1;
                }
            }
            #pragma unroll
            for (int i = 0; i < 4; ++i) {
                p[i] += __shfl_xor_sync(0xffffffffu, p[i], 1);
                p[i] += __shfl_xor_sync(0xffffffffu, p[i], 2);
                q[i] += __shfl_xor_sync(0xffffffffu, q[i], 1);
                q[i] += __shfl_xor_sync(0xffffffffu, q[i], 2);
            }
            if (tig == 0) {
                #pragma unroll
                for (int rg = 0; rg < 2; ++rg) {
                    int rA = r0 + rg * 16 + g, rB = rA + 8;
                    sD1[rA * 4 + wc] = p[rg * 2 + 0];
                    sD1[rB * 4 + wc] = p[rg * 2 + 1];
                    sD2[rA * 4 + wc] = q[rg * 2 + 0];
                    sD2[rB * 4 + wc] = q[rg * 2 + 1];
                }
            }
        }

        // ---- store mapped = xn @ W (fp16) ----
        #pragma unroll
        for (int t = 0; t < 2; ++t) {
            int c0 = wc * 16 + t * 8 + 2 * tig;
            #pragma unroll
            for (int rg = 0; rg < 2; ++rg) {
                int gA = node0 + r0 + rg * 16 + g, gB = gA + 8;
                if (gA < N_NODES)
                    g_mapped16[(size_t)gA * 32 + (c0 >> 1)] =
                        __floats2half2_rn(aW[t * 2 + rg][0], aW[t * 2 + rg][1]);
                if (gB < N_NODES)
                    g_mapped16[(size_t)gB * 32 + (c0 >> 1)] =
                        __floats2half2_rn(aW[t * 2 + rg][2], aW[t * 2 + rg][3]);
            }
        }

        __syncthreads();
        if (tid < 64) {
            int gn = node0 + tid;
            if (gn < N_NODES) {
                g_a1[gn] = tanhf(sD1[tid * 4] + sD1[tid * 4 + 1] + sD1[tid * 4 + 2] + sD1[tid * 4 + 3]);
                g_a2[gn] = tanhf(sD2[tid * 4] + sD2[tid * 4 + 1] + sD2[tid * 4 + 2] + sD2[tid * 4 + 3]);
            }
        }
    }
}

// ---------------- fused softmax + SpMM + tanh (R10 winner, untouched) -----------
__global__ void k_spmm(float* __restrict__ out) {
    __shared__ int2 sed[8][32];
    int w = threadIdx.x >> 5;
    int node = blockIdx.x * 8 + w;
    if (node >= N_NODES) return;
    int lane = threadIdx.x & 31;
    int s = g_rowptr[node];
    int e = g_rowptr[node + 1];
    float a1i = g_a1[node];

    float2 acc = make_float2(0.f, 0.f);
    float den = 0.f;

    for (int base = s; base < e; base += 32) {
        int j = base + lane;
        int d = 0; float wgt = 0.f;
        if (j < e) {
            int2 ed = g_cedge[j];
            d = ed.x;
            float v = __int_as_float(ed.y);
            float t = v * (a1i + g_a2[d]);
            t = t > 0.f ? t : 0.2f * t;
            wgt = __expf(t);
        }
        sed[w][lane] = make_int2(d, __float_as_int(wgt));
        __syncwarp();
        int m = min(32, e - base);
        #pragma unroll 4
        for (int jj = 0; jj < m; ++jj) {
            int2 ed = sed[w][jj];
            float wj = __int_as_float(ed.y);
            float2 md = __half22float2(g_mapped16[(size_t)ed.x * 32 + lane]);
            den += wj;
            acc.x += wj * md.x;
            acc.y += wj * md.y;
        }
        __syncwarp();
    }
    float2 o;
    if (e > s) {
        float inv = 1.f / den;
        o.x = tanhf(acc.x * inv);
        o.y = tanhf(acc.y * inv);
    } else {
        o = make_float2(0.f, 0.f);
    }
    ((float2*)out)[(size_t)node * 32 + lane] = o;
}

// ---------------- launch (R10/R11 structure; gemm in profiled 4th slot) ----------
extern "C" void kernel_launch(void* const* d_in, const int* in_sizes, int n_in,
                              void* d_out, int out_size) {
    const float* x    = (const float*)d_in[0];
    const int*   src  = (const int*)d_in[1];
    const int*   dst  = (const int*)d_in[2];
    const float* vals = (const float*)d_in[3];
    const float* W    = (const float*)d_in[4];
    const float* K1   = (const float*)d_in[5];
    const float* K2   = (const float*)d_in[6];
    float* out = (float*)d_out;

    static cudaStream_t s2 = nullptr;
    static cudaEvent_t evA = nullptr, evB = nullptr;
    if (!s2) {
        cudaStreamCreateWithFlags(&s2, cudaStreamNonBlocking);
        cudaEventCreateWithFlags(&evA, cudaEventDisableTiming);
        cudaEventCreateWithFlags(&evB, cudaEventDisableTiming);
    }

    const int NB = (N_NODES + 1023) / 1024;
    const int EB = (N_EDGES + 255) / 256;

    cudaEventRecord(evA, 0);
    cudaStreamWaitEvent(s2, evA, 0);

    k_colstats<<<592, 256>>>(x);                     // 1 (main)
    k_finalize_stats<<<1, 128>>>();                  // 2 (main)
    k_zero_deg<<<256, 256, 0, s2>>>();               // 3 (s2)
    size_t smem = (size_t)(4 * F_IN * PADK + 2 * D_OUT * PADK + 2 * 64 * PADK) * sizeof(__nv_bfloat16)
                + 512 * sizeof(float);
    cudaFuncSetAttribute(k_gemm, cudaFuncAttributeMaxDynamicSharedMemorySize, (int)smem);
    k_gemm<<<148, 256, smem>>>(x, K1, K2, W);        // 4 (main) <-- profiled

    k_hist<<<EB, 256, 0, s2>>>(src);                 // 5 (s2)
    k_scan1<<<NB, 1024, 0, s2>>>();                  // 6 (s2)
    k_scan2<<<1, 128, 0, s2>>>(NB);                  // 7 (s2)
    k_scan3<<<NB, 1024, 0, s2>>>();                  // 8 (s2)
    k_scatter<<<EB, 256, 0, s2>>>(src, dst, vals);   // 9 (s2)
    cudaEventRecord(evB, s2);

    cudaStreamWaitEvent(0, evB, 0);
    k_spmm<<<(N_NODES + 7) / 8, 256>>>(out);         // 10 (main)
}